// round 3
// baseline (speedup 1.0000x reference)
#include <cuda_runtime.h>
#include <math.h>

#define DIM   1024
#define NH    16
#define HD    64
#define HALF  32
#define BATCH 2
#define SEQ   2048
#define MTOT  (BATCH*SEQ)   // 4096

// ---------------- scratch (device globals; no allocation allowed) ----------------
__device__ float g_q[BATCH*NH*SEQ*HD];      // 16 MB  [B,H,L,hd]
__device__ float g_k[BATCH*NH*SEQ*HD];      // 16 MB
__device__ float g_v[BATCH*NH*SEQ*HD];      // 16 MB
__device__ float g_attn[MTOT*DIM];          // 16 MB  [B*L, D]
__device__ float g_cos[SEQ*HALF];
__device__ float g_sin[SEQ*HALF];

// ---------------- RoPE tables (fp64 for accurate range reduction) ----------------
__global__ void rope_table_kernel() {
    int idx = blockIdx.x * blockDim.x + threadIdx.x;
    if (idx >= SEQ*HALF) return;
    int l = idx / HALF, i = idx % HALF;
    double invf = pow(10000.0, -(double)i / (double)HALF);
    double a = (double)l * invf;
    double s, c;
    sincos(a, &s, &c);
    g_cos[idx] = (float)c;
    g_sin[idx] = (float)s;
}

// ---------------- fused QKV GEMM + RoPE epilogue ---------------------------------
// grid (24, 32): bn 0..7 -> Q, 8..15 -> K, 16..23 -> V.  128x128x32 tiles.
// C[m,n] = sum_k x[m,k]*W[n,k]; q,k rows get RoPE applied in registers.
__global__ void __launch_bounds__(256) gemm_qkv_kernel(const float* __restrict__ x,
                                                       const float* __restrict__ wq,
                                                       const float* __restrict__ wk,
                                                       const float* __restrict__ wv) {
    __shared__ float As[128*32];
    __shared__ float Bs[128*32];

    int tid = threadIdx.x;
    int tx = tid & 15, ty = tid >> 4;
    int bm = blockIdx.y, bn = blockIdx.x;
    const float* W   = (bn < 8) ? wq  : (bn < 16) ? wk  : wv;
    float*       dst = (bn < 8) ? g_q : (bn < 16) ? g_k : g_v;
    bool is_v = (bn >= 16);
    int bnl = bn & 7;

    float acc[8][8];
    #pragma unroll
    for (int i = 0; i < 8; ++i)
        #pragma unroll
        for (int j = 0; j < 8; ++j) acc[i][j] = 0.f;

    const float* Ab = x + (size_t)(bm*128) * 1024;
    const float* Wb = W + (size_t)(bnl*128) * 1024;
    int lr  = tid >> 3;   // 0..31
    int lc4 = tid & 7;    // 0..7

    for (int kt = 0; kt < 32; ++kt) {
        #pragma unroll
        for (int it = 0; it < 4; ++it) {
            int row = lr + 32*it;
            float4 av = *(const float4*)&Ab[(size_t)row*1024 + kt*32 + lc4*4];
            *(float4*)&As[row*32 + ((lc4 ^ (row & 7)) << 2)] = av;
            float4 bv = *(const float4*)&Wb[(size_t)row*1024 + kt*32 + lc4*4];
            *(float4*)&Bs[row*32 + ((lc4 ^ (row & 7)) << 2)] = bv;
        }
        __syncthreads();
        #pragma unroll
        for (int k4 = 0; k4 < 8; ++k4) {
            int ao = (k4 ^ (ty & 7)) << 2;
            int bo = (k4 ^ (tx & 7)) << 2;
            float4 a[8];
            #pragma unroll
            for (int i = 0; i < 8; ++i) a[i] = *(const float4*)&As[(ty + 16*i)*32 + ao];
            #pragma unroll
            for (int j = 0; j < 8; ++j) {
                float4 b = *(const float4*)&Bs[(tx + 16*j)*32 + bo];
                #pragma unroll
                for (int i = 0; i < 8; ++i)
                    acc[i][j] += a[i].x*b.x + a[i].y*b.y + a[i].z*b.z + a[i].w*b.w;
            }
        }
        __syncthreads();
    }

    #pragma unroll
    for (int i = 0; i < 8; ++i) {
        int m  = bm*128 + ty + 16*i;
        int b_ = m >> 11, l_ = m & 2047;
        if (!is_v) {
            // RoPE: columns c=tx+16*j; pair (d, d+32) lives at (j, j+2), j in {0,1,4,5}
            #pragma unroll
            for (int jj = 0; jj < 4; ++jj) {
                int j = (jj < 2) ? jj : jj + 2;
                int d2 = (tx + 16*j) & 31;
                float cth = g_cos[l_*HALF + d2];
                float sth = g_sin[l_*HALF + d2];
                float x1 = acc[i][j], x2 = acc[i][j+2];
                acc[i][j]   = x1*cth - x2*sth;
                acc[i][j+2] = x2*cth + x1*sth;
            }
        }
        #pragma unroll
        for (int j = 0; j < 8; ++j) {
            int n = bnl*128 + tx + 16*j;
            int h = n >> 6, d = n & 63;
            dst[(((size_t)(b_*NH + h))*SEQ + l_)*HD + d] = acc[i][j];
        }
    }
}

// ---------------- output projection GEMM: out = g_attn @ wo^T --------------------
__global__ void __launch_bounds__(256) gemm_out_kernel(const float* __restrict__ W,
                                                       float* __restrict__ Cout) {
    __shared__ float As[128*32];
    __shared__ float Bs[128*32];

    int tid = threadIdx.x;
    int tx = tid & 15, ty = tid >> 4;
    int bm = blockIdx.y, bn = blockIdx.x;

    float acc[8][8];
    #pragma unroll
    for (int i = 0; i < 8; ++i)
        #pragma unroll
        for (int j = 0; j < 8; ++j) acc[i][j] = 0.f;

    const float* Ab = g_attn + (size_t)(bm*128) * 1024;
    const float* Wb = W + (size_t)(bn*128) * 1024;
    int lr  = tid >> 3;
    int lc4 = tid & 7;

    for (int kt = 0; kt < 32; ++kt) {
        #pragma unroll
        for (int it = 0; it < 4; ++it) {
            int row = lr + 32*it;
            float4 av = *(const float4*)&Ab[(size_t)row*1024 + kt*32 + lc4*4];
            *(float4*)&As[row*32 + ((lc4 ^ (row & 7)) << 2)] = av;
            float4 bv = *(const float4*)&Wb[(size_t)row*1024 + kt*32 + lc4*4];
            *(float4*)&Bs[row*32 + ((lc4 ^ (row & 7)) << 2)] = bv;
        }
        __syncthreads();
        #pragma unroll
        for (int k4 = 0; k4 < 8; ++k4) {
            int ao = (k4 ^ (ty & 7)) << 2;
            int bo = (k4 ^ (tx & 7)) << 2;
            float4 a[8];
            #pragma unroll
            for (int i = 0; i < 8; ++i) a[i] = *(const float4*)&As[(ty + 16*i)*32 + ao];
            #pragma unroll
            for (int j = 0; j < 8; ++j) {
                float4 b = *(const float4*)&Bs[(tx + 16*j)*32 + bo];
                #pragma unroll
                for (int i = 0; i < 8; ++i)
                    acc[i][j] += a[i].x*b.x + a[i].y*b.y + a[i].z*b.z + a[i].w*b.w;
            }
        }
        __syncthreads();
    }

    #pragma unroll
    for (int i = 0; i < 8; ++i) {
        int m = bm*128 + ty + 16*i;
        #pragma unroll
        for (int j = 0; j < 8; ++j) {
            int n = bn*128 + tx + 16*j;
            Cout[(size_t)m*DIM + n] = acc[i][j];
        }
    }
}

// ---------------- Flash attention: per (b,h), 64-query tiles, 64-key tiles -------
// 48 KB static smem (P tile aliases K tile after S=QK^T is consumed) -> 2 CTAs/SM.
__global__ void __launch_bounds__(256) attn_kernel() {
    __shared__ float sm[12288];
    float* Qs = sm;            // 64*64, swizzled
    float* Ks = sm + 4096;     // 64*64, swizzled; reused as Ps after S compute
    float* Vs = sm + 8192;     // 64*64, natural
    float* Ps = Ks;            // alias

    int tid = threadIdx.x;
    int tx = tid & 15, ty = tid >> 4;
    int qb = blockIdx.x;       // 0..31
    int bh = blockIdx.y;       // 0..31
    const float* Qg = g_q + (size_t)bh*SEQ*HD + (size_t)qb*64*HD;
    const float* Kg = g_k + (size_t)bh*SEQ*HD;
    const float* Vg = g_v + (size_t)bh*SEQ*HD;

    // load Q tile (swizzled)
    {
        int lr = tid >> 4, lc4 = tid & 15;
        #pragma unroll
        for (int it = 0; it < 4; ++it) {
            int row = lr + 16*it;
            float4 v = *(const float4*)&Qg[row*64 + lc4*4];
            *(float4*)&Qs[row*64 + ((lc4 ^ (row & 7)) << 2)] = v;
        }
    }

    float m_i[4], l_i[4], o[4][4];
    #pragma unroll
    for (int i = 0; i < 4; ++i) {
        m_i[i] = -INFINITY; l_i[i] = 0.f;
        #pragma unroll
        for (int j = 0; j < 4; ++j) o[i][j] = 0.f;
    }

    for (int kb = 0; kb < 32; ++kb) {
        __syncthreads();  // prior iteration finished reading Ps(=Ks)/Vs; Q store visible
        {
            int lr = tid >> 4, lc4 = tid & 15;
            #pragma unroll
            for (int it = 0; it < 4; ++it) {
                int row = lr + 16*it;
                float4 kv = *(const float4*)&Kg[(size_t)(kb*64 + row)*64 + lc4*4];
                *(float4*)&Ks[row*64 + ((lc4 ^ (row & 7)) << 2)] = kv;
                float4 vv = *(const float4*)&Vg[(size_t)(kb*64 + row)*64 + lc4*4];
                *(float4*)&Vs[row*64 + lc4*4] = vv;
            }
        }
        __syncthreads();

        // S = Q K^T (per-thread 4x4: rows ty+16i, cols tx+16j)
        float s[4][4];
        #pragma unroll
        for (int i = 0; i < 4; ++i)
            #pragma unroll
            for (int j = 0; j < 4; ++j) s[i][j] = 0.f;

        #pragma unroll
        for (int k4 = 0; k4 < 16; ++k4) {
            int ao = (k4 ^ (ty & 7)) << 2;
            int bo = (k4 ^ (tx & 7)) << 2;
            float4 a[4];
            #pragma unroll
            for (int i = 0; i < 4; ++i) a[i] = *(const float4*)&Qs[(ty + 16*i)*64 + ao];
            #pragma unroll
            for (int j = 0; j < 4; ++j) {
                float4 b = *(const float4*)&Ks[(tx + 16*j)*64 + bo];
                #pragma unroll
                for (int i = 0; i < 4; ++i)
                    s[i][j] += a[i].x*b.x + a[i].y*b.y + a[i].z*b.z + a[i].w*b.w;
            }
        }
        __syncthreads();   // everyone done reading Ks before Ps (alias) is written

        // online softmax per row; write P tile (swizzled) into Ks slot
        #pragma unroll
        for (int i = 0; i < 4; ++i) {
            float mx = -INFINITY;
            #pragma unroll
            for (int j = 0; j < 4; ++j) { s[i][j] *= 0.125f; mx = fmaxf(mx, s[i][j]); }
            #pragma unroll
            for (int msk = 1; msk < 16; msk <<= 1)
                mx = fmaxf(mx, __shfl_xor_sync(0xffffffffu, mx, msk));
            float mn = fmaxf(m_i[i], mx);
            float alpha = __expf(m_i[i] - mn);
            m_i[i] = mn;
            float rs = 0.f;
            #pragma unroll
            for (int j = 0; j < 4; ++j) { s[i][j] = __expf(s[i][j] - mn); rs += s[i][j]; }
            #pragma unroll
            for (int msk = 1; msk < 16; msk <<= 1)
                rs += __shfl_xor_sync(0xffffffffu, rs, msk);
            l_i[i] = l_i[i]*alpha + rs;
            #pragma unroll
            for (int j = 0; j < 4; ++j) o[i][j] *= alpha;
            int r = ty + 16*i;
            #pragma unroll
            for (int j = 0; j < 4; ++j) {
                int c = tx + 16*j;
                Ps[r*64 + ((((c >> 2) ^ (r & 7)) << 2) | (c & 3))] = s[i][j];
            }
        }
        __syncthreads();

        // O += P V   (P fragments as float4 along k; V rows natural)
        #pragma unroll
        for (int k24 = 0; k24 < 16; ++k24) {
            int po = (k24 ^ (ty & 7)) << 2;
            float4 pa[4];
            #pragma unroll
            for (int i = 0; i < 4; ++i) pa[i] = *(const float4*)&Ps[(ty + 16*i)*64 + po];
            #pragma unroll
            for (int q = 0; q < 4; ++q) {
                int k2 = k24*4 + q;
                float vb[4];
                #pragma unroll
                for (int j = 0; j < 4; ++j) vb[j] = Vs[k2*64 + tx + 16*j];
                #pragma unroll
                for (int i = 0; i < 4; ++i) {
                    float p = (q == 0) ? pa[i].x : (q == 1) ? pa[i].y : (q == 2) ? pa[i].z : pa[i].w;
                    #pragma unroll
                    for (int j = 0; j < 4; ++j) o[i][j] += p * vb[j];
                }
            }
        }
    }

    // write to g_attn in [B*L, D] layout
    int b_ = bh >> 4, h = bh & 15;
    #pragma unroll
    for (int i = 0; i < 4; ++i) {
        int l_ = qb*64 + ty + 16*i;
        float inv = 1.0f / l_i[i];
        #pragma unroll
        for (int j = 0; j < 4; ++j) {
            int c = tx + 16*j;
            g_attn[((size_t)(b_*SEQ + l_))*DIM + h*64 + c] = o[i][j] * inv;
        }
    }
}

// ---------------- launch ----------------
extern "C" void kernel_launch(void* const* d_in, const int* in_sizes, int n_in,
                              void* d_out, int out_size) {
    const float* x  = (const float*)d_in[0];
    const float* wq = (const float*)d_in[1];
    const float* wk = (const float*)d_in[2];
    const float* wv = (const float*)d_in[3];
    const float* wo = (const float*)d_in[4];
    float* out = (float*)d_out;

    rope_table_kernel<<<256, 256>>>();
    gemm_qkv_kernel<<<dim3(24, 32), 256>>>(x, wq, wk, wv);
    attn_kernel<<<dim3(32, 32), 256>>>();
    gemm_out_kernel<<<dim3(8, 32), 256>>>(wo, out);
}

// round 6
// speedup vs baseline: 1.5402x; 1.5402x over previous
#include <cuda_runtime.h>
#include <cuda_bf16.h>
#include <cstdint>
#include <math.h>

#define DIM   1024
#define NH    16
#define HD    64
#define HALF  32
#define BATCH 2
#define SEQ   2048
#define MTOT  (BATCH*SEQ)
#define NELEM (MTOT*DIM)

// ---------------- scratch (device globals; no allocation allowed) ----------------
__device__ float g_q[BATCH*NH*SEQ*HD];
__device__ float g_k[BATCH*NH*SEQ*HD];
__device__ float g_v[BATCH*NH*SEQ*HD];
__device__ float g_attn[NELEM];
__device__ float g_cos[SEQ*HALF];
__device__ float g_sin[SEQ*HALF];
__device__ __nv_bfloat16 g_xh[NELEM];
__device__ __nv_bfloat16 g_xl[NELEM];
__device__ __nv_bfloat16 g_wh[NELEM];
__device__ __nv_bfloat16 g_wl[NELEM];
__device__ __nv_bfloat16 g_ah[NELEM];
__device__ __nv_bfloat16 g_al[NELEM];

// ---------------- RoPE tables ----------------
__global__ void rope_table_kernel() {
    int idx = blockIdx.x * blockDim.x + threadIdx.x;
    if (idx >= SEQ*HALF) return;
    int l = idx / HALF, i = idx % HALF;
    double invf = pow(10000.0, -(double)i / (double)HALF);
    double a = (double)l * invf;
    double s, c;
    sincos(a, &s, &c);
    g_cos[idx] = (float)c;
    g_sin[idx] = (float)s;
}

// ---------------- mma helpers ----------------
__device__ __forceinline__ void ldm4(uint32_t& r0, uint32_t& r1, uint32_t& r2, uint32_t& r3,
                                     uint32_t addr) {
    asm volatile("ldmatrix.sync.aligned.m8n8.x4.shared.b16 {%0,%1,%2,%3}, [%4];"
                 : "=r"(r0), "=r"(r1), "=r"(r2), "=r"(r3) : "r"(addr));
}

__device__ __forceinline__ void mma16816(float* c, const uint32_t* a, const uint32_t* b) {
    asm volatile("mma.sync.aligned.m16n8k16.row.col.f32.bf16.bf16.f32 "
                 "{%0,%1,%2,%3},{%4,%5,%6,%7},{%8,%9},{%0,%1,%2,%3};"
                 : "+f"(c[0]), "+f"(c[1]), "+f"(c[2]), "+f"(c[3])
                 : "r"(a[0]), "r"(a[1]), "r"(a[2]), "r"(a[3]), "r"(b[0]), "r"(b[1]));
}

__device__ __forceinline__ int sidx(int row, int c) {
    return (row * 4 + (c ^ ((row >> 1) & 3))) * 8;
}

// ---------------- core bf16x3 tile loop (shared by both GEMM kernels) -------------
// Computes acc[4][4][4] for a 128x128 C tile, K=1024, KC=32 chunks.
__device__ __forceinline__ void mma_tile_loop(
    const __nv_bfloat16* __restrict__ Ah, const __nv_bfloat16* __restrict__ Al,
    const __nv_bfloat16* __restrict__ Bh, const __nv_bfloat16* __restrict__ Bl,
    int bm, int bnl, int lane, int wrp, int warpM, int warpN,
    __nv_bfloat16* sAh, __nv_bfloat16* sAl, __nv_bfloat16* sBh, __nv_bfloat16* sBl,
    float acc[4][4][4])
{
    const uint32_t bAh = (uint32_t)__cvta_generic_to_shared(sAh);
    const uint32_t bAl = (uint32_t)__cvta_generic_to_shared(sAl);
    const uint32_t bBh = (uint32_t)__cvta_generic_to_shared(sBh);
    const uint32_t bBl = (uint32_t)__cvta_generic_to_shared(sBl);

    for (int kt = 0; kt < 32; ++kt) {
        #pragma unroll
        for (int it = 0; it < 2; ++it) {
            int slot = lane + 32 * it;
            int row = 16 * wrp + (slot >> 2);
            int c = slot & 3;
            int so = sidx(row, c);
            size_t ga = (size_t)(bm * 128 + row) * 1024 + (size_t)(kt * 32 + c * 8);
            size_t gb = (size_t)(bnl * 128 + row) * 1024 + (size_t)(kt * 32 + c * 8);
            *(uint4*)(sAh + so) = *(const uint4*)(Ah + ga);
            *(uint4*)(sAl + so) = *(const uint4*)(Al + ga);
            *(uint4*)(sBh + so) = *(const uint4*)(Bh + gb);
            *(uint4*)(sBl + so) = *(const uint4*)(Bl + gb);
        }
        __syncthreads();

        #pragma unroll
        for (int kk = 0; kk < 2; ++kk) {
            uint32_t afh[4][4];
            uint32_t afl[4][4];
            #pragma unroll
            for (int mt = 0; mt < 4; ++mt) {
                int rA = 64 * warpM + 16 * mt + (lane & 7) + ((lane >> 3) & 1) * 8;
                int cA = 2 * kk + (lane >> 4);
                uint32_t off = (uint32_t)(sidx(rA, cA) * 2);
                ldm4(afh[mt][0], afh[mt][1], afh[mt][2], afh[mt][3], bAh + off);
                ldm4(afl[mt][0], afl[mt][1], afl[mt][2], afl[mt][3], bAl + off);
            }
            uint32_t bfh[4][2];
            uint32_t bfl[4][2];
            #pragma unroll
            for (int g2 = 0; g2 < 2; ++g2) {
                int rB = 8 * warpN + 64 * g2 + 32 * (lane >> 4) + (lane & 7);
                int cB = 2 * kk + ((lane >> 3) & 1);
                uint32_t off = (uint32_t)(sidx(rB, cB) * 2);
                uint32_t r0, r1, r2, r3;
                ldm4(r0, r1, r2, r3, bBh + off);
                bfh[2*g2][0] = r0;
                bfh[2*g2][1] = r1;
                bfh[2*g2+1][0] = r2;
                bfh[2*g2+1][1] = r3;
                ldm4(r0, r1, r2, r3, bBl + off);
                bfl[2*g2][0] = r0;
                bfl[2*g2][1] = r1;
                bfl[2*g2+1][0] = r2;
                bfl[2*g2+1][1] = r3;
            }
            #pragma unroll
            for (int mt = 0; mt < 4; ++mt) {
                #pragma unroll
                for (int tn = 0; tn < 4; ++tn) {
                    mma16816(acc[mt][tn], afh[mt], bfh[tn]);
                    mma16816(acc[mt][tn], afh[mt], bfl[tn]);
                    mma16816(acc[mt][tn], afl[mt], bfh[tn]);
                }
            }
        }
        __syncthreads();
    }
}

// ---------------- QKV GEMM + fused RoPE ----------------
// grid (24, 32): bn 0..7 -> Q, 8..15 -> K, 16..23 -> V.
__global__ void __launch_bounds__(256) mma_qkv_kernel() {
    __shared__ __align__(16) __nv_bfloat16 sAh[4096];
    __shared__ __align__(16) __nv_bfloat16 sAl[4096];
    __shared__ __align__(16) __nv_bfloat16 sBh[4096];
    __shared__ __align__(16) __nv_bfloat16 sBl[4096];

    const int tid = threadIdx.x;
    const int lane = tid & 31;
    const int wrp = tid >> 5;
    const int warpM = wrp >> 2;
    const int warpN = wrp & 3;
    const int bm = blockIdx.y;
    const int bn = blockIdx.x;
    const int wsel = bn >> 3;
    const int bnl = bn & 7;

    const __nv_bfloat16* Bh = g_wh + (size_t)wsel * 1048576u;
    const __nv_bfloat16* Bl = g_wl + (size_t)wsel * 1048576u;

    float acc[4][4][4];
    #pragma unroll
    for (int i = 0; i < 4; ++i) {
        #pragma unroll
        for (int j = 0; j < 4; ++j) {
            #pragma unroll
            for (int e = 0; e < 4; ++e) {
                acc[i][j][e] = 0.f;
            }
        }
    }

    mma_tile_loop(g_xh, g_xl, Bh, Bl, bm, bnl, lane, wrp, warpM, warpN,
                  sAh, sAl, sBh, sBl, acc);

    const int g = lane >> 2;
    const int tig = lane & 3;
    const bool is_v = (bn >= 16);
    float* dst = (bn < 8) ? g_q : ((bn < 16) ? g_k : g_v);

    #pragma unroll
    for (int mt = 0; mt < 4; ++mt) {
        #pragma unroll
        for (int eh = 0; eh < 2; ++eh) {
            int m = bm * 128 + 64 * warpM + 16 * mt + g + 8 * eh;
            int b_ = m >> 11;
            int l_ = m & 2047;
            if (!is_v) {
                #pragma unroll
                for (int el = 0; el < 2; ++el) {
                    int d2 = 8 * warpN + 2 * tig + el;
                    float cth = g_cos[l_ * HALF + d2];
                    float sth = g_sin[l_ * HALF + d2];
                    int e = 2 * eh + el;
                    float x1 = acc[mt][0][e];
                    float x2 = acc[mt][1][e];
                    acc[mt][0][e] = x1 * cth - x2 * sth;
                    acc[mt][1][e] = x2 * cth + x1 * sth;
                    x1 = acc[mt][2][e];
                    x2 = acc[mt][3][e];
                    acc[mt][2][e] = x1 * cth - x2 * sth;
                    acc[mt][3][e] = x2 * cth + x1 * sth;
                }
            }
            #pragma unroll
            for (int tn = 0; tn < 4; ++tn) {
                int n = bnl * 128 + 8 * warpN + 32 * tn + 2 * tig;
                int h = n >> 6;
                int d = n & 63;
                float2 v2 = make_float2(acc[mt][tn][2*eh], acc[mt][tn][2*eh+1]);
                *(float2*)&dst[(((size_t)(b_ * NH + h)) * SEQ + l_) * HD + d] = v2;
            }
        }
    }
}

// ---------------- output projection GEMM ----------------
__global__ void __launch_bounds__(256) mma_out_kernel(float* __restrict__ out) {
    __shared__ __align__(16) __nv_bfloat16 sAh[4096];
    __shared__ __align__(16) __nv_bfloat16 sAl[4096];
    __shared__ __align__(16) __nv_bfloat16 sBh[4096];
    __shared__ __align__(16) __nv_bfloat16 sBl[4096];

    const int tid = threadIdx.x;
    const int lane = tid & 31;
    const int wrp = tid >> 5;
    const int warpM = wrp >> 2;
    const int warpN = wrp & 3;
    const int bm = blockIdx.y;
    const int bnl = blockIdx.x;

    const __nv_bfloat16* Bh = g_wh + (size_t)3 * 1048576u;
    const __nv_bfloat16* Bl = g_wl + (size_t)3 * 1048576u;

    float acc[4][4][4];
    #pragma unroll
    for (int i = 0; i < 4; ++i) {
        #pragma unroll
        for (int j = 0; j < 4; ++j) {
            #pragma unroll
            for (int e = 0; e < 4; ++e) {
                acc[i][j][e] = 0.f;
            }
        }
    }

    mma_tile_loop(g_ah, g_al, Bh, Bl, bm, bnl, lane, wrp, warpM, warpN,
                  sAh, sAl, sBh, sBl, acc);

    const int g = lane >> 2;
    const int tig = lane & 3;
    #pragma unroll
    for (int mt = 0; mt < 4; ++mt) {
        #pragma unroll
        for (int eh = 0; eh < 2; ++eh) {
            int m = bm * 128 + 64 * warpM + 16 * mt + g + 8 * eh;
            #pragma unroll
            for (int tn = 0; tn < 4; ++tn) {
                int n = bnl * 128 + 8 * warpN + 32 * tn + 2 * tig;
                float2 v2 = make_float2(acc[mt][tn][2*eh], acc[mt][tn][2*eh+1]);
                *(float2*)&out[(size_t)m * DIM + n] = v2;
            }
        }
    }
}

// ---------------- Flash attention (fp32, verified in Round 3) ----------------
__global__ void __launch_bounds__(256) attn_kernel() {
    __shared__ float sm[12288];
    float* Qs = sm;
    float* Ks = sm + 4096;
    float* Vs = sm + 8192;
    float* Ps = Ks;

    int tid = threadIdx.x;
    int tx = tid & 15, ty = tid >> 4;
    int qb = blockIdx.x;
    int bh = blockIdx.y;
    const float* Qg = g_q + (size_t)bh*SEQ*HD + (size_t)qb*64*HD;
    const float* Kg = g_k + (size_t)bh*SEQ*HD;
    const float* Vg = g_v + (size_t)bh*SEQ*HD;

    {
        int lr = tid >> 4, lc4 = tid & 15;
        #pragma unroll
        for (int it = 0; it < 4; ++it) {
            int row = lr + 16*it;
            float4 v = *(const float4*)&Qg[row*64 + lc4*4];
            *(float4*)&Qs[row*64 + ((lc4 ^ (row & 7)) << 2)] = v;
        }
    }

    float m_i[4], l_i[4], o[4][4];
    #pragma unroll
    for (int i = 0; i < 4; ++i) {
        m_i[i] = -INFINITY;
        l_i[i] = 0.f;
        #pragma unroll
        for (int j = 0; j < 4; ++j) {
            o[i][j] = 0.f;
        }
    }

    for (int kb = 0; kb < 32; ++kb) {
        __syncthreads();
        {
            int lr = tid >> 4, lc4 = tid & 15;
            #pragma unroll
            for (int it = 0; it < 4; ++it) {
                int row = lr + 16*it;
                float4 kv = *(const float4*)&Kg[(size_t)(kb*64 + row)*64 + lc4*4];
                *(float4*)&Ks[row*64 + ((lc4 ^ (row & 7)) << 2)] = kv;
                float4 vv = *(const float4*)&Vg[(size_t)(kb*64 + row)*64 + lc4*4];
                *(float4*)&Vs[row*64 + lc4*4] = vv;
            }
        }
        __syncthreads();

        float s[4][4];
        #pragma unroll
        for (int i = 0; i < 4; ++i) {
            #pragma unroll
            for (int j = 0; j < 4; ++j) {
                s[i][j] = 0.f;
            }
        }

        #pragma unroll
        for (int k4 = 0; k4 < 16; ++k4) {
            int ao = (k4 ^ (ty & 7)) << 2;
            int bo = (k4 ^ (tx & 7)) << 2;
            float4 a[4];
            #pragma unroll
            for (int i = 0; i < 4; ++i) {
                a[i] = *(const float4*)&Qs[(ty + 16*i)*64 + ao];
            }
            #pragma unroll
            for (int j = 0; j < 4; ++j) {
                float4 b = *(const float4*)&Ks[(tx + 16*j)*64 + bo];
                #pragma unroll
                for (int i = 0; i < 4; ++i) {
                    s[i][j] += a[i].x*b.x + a[i].y*b.y + a[i].z*b.z + a[i].w*b.w;
                }
            }
        }
        __syncthreads();

        #pragma unroll
        for (int i = 0; i < 4; ++i) {
            float mx = -INFINITY;
            #pragma unroll
            for (int j = 0; j < 4; ++j) {
                s[i][j] *= 0.125f;
                mx = fmaxf(mx, s[i][j]);
            }
            #pragma unroll
            for (int msk = 1; msk < 16; msk <<= 1) {
                mx = fmaxf(mx, __shfl_xor_sync(0xffffffffu, mx, msk));
            }
            float mn = fmaxf(m_i[i], mx);
            float alpha = __expf(m_i[i] - mn);
            m_i[i] = mn;
            float rs = 0.f;
            #pragma unroll
            for (int j = 0; j < 4; ++j) {
                s[i][j] = __expf(s[i][j] - mn);
                rs += s[i][j];
            }
            #pragma unroll
            for (int msk = 1; msk < 16; msk <<= 1) {
                rs += __shfl_xor_sync(0xffffffffu, rs, msk);
            }
            l_i[i] = l_i[i]*alpha + rs;
            #pragma unroll
            for (int j = 0; j < 4; ++j) {
                o[i][j] *= alpha;
            }
            int r = ty + 16*i;
            #pragma unroll
            for (int j = 0; j < 4; ++j) {
                int c = tx + 16*j;
                Ps[r*64 + ((((c >> 2) ^ (r & 7)) << 2) | (c & 3))] = s[i][j];
            }
        }
        __syncthreads();

        #pragma unroll
        for (int k24 = 0; k24 < 16; ++k24) {
            int po = (k24 ^ (ty & 7)) << 2;
            float4 pa[4];
            #pragma unroll
            for (int i = 0; i < 4; ++i) {
                pa[i] = *(const float4*)&Ps[(ty + 16*i)*64 + po];
            }
            #pragma unroll
            for (int q = 0; q < 4; ++q) {
                int k2 = k24*4 + q;
                float vb[4];
                #pragma unroll
                for (int j = 0; j < 4; ++j) {
                    vb[j] = Vs[k2*64 + tx + 16*j];
                }
                #pragma unroll
                for (int i = 0; i < 4; ++i) {
                    float p = (q == 0) ? pa[i].x : ((q == 1) ? pa[i].y : ((q == 2) ? pa[i].z : pa[i].w));
                    #pragma unroll
                    for (int j = 0; j < 4; ++j) {
                        o[i][j] += p * vb[j];
                    }
                }
            }
        }
    }

    int b_ = bh >> 4;
    int h = bh & 15;
    #pragma unroll
    for (int i = 0; i < 4; ++i) {
        int l_ = qb*64 + ty + 16*i;
        float inv = 1.0f / l_i[i];
        #pragma unroll
        for (int j = 0; j < 4; ++j) {
            int c = tx + 16*j;
            g_attn[((size_t)(b_*SEQ + l_))*DIM + h*64 + c] = o[i][j] * inv;
        }
    }
}

// ---------------- fp32 -> bf16 hi/lo split ----------------
// which: 0..3 weight block -> g_wh/g_wl + which*1M; 4 -> x; 5 -> g_attn.
__global__ void conv_dev_kernel(int which, const float* __restrict__ src_param) {
    const float* src;
    __nv_bfloat16* hi;
    __nv_bfloat16* lo;
    if (which <= 3) {
        src = src_param;
        hi = g_wh + (size_t)which * 1048576u;
        lo = g_wl + (size_t)which * 1048576u;
    } else if (which == 4) {
        src = src_param;
        hi = g_xh;
        lo = g_xl;
    } else {
        src = g_attn;
        hi = g_ah;
        lo = g_al;
    }
    int i = (blockIdx.x * blockDim.x + threadIdx.x) * 4;
    float4 v = *(const float4*)(src + i);
    __nv_bfloat16 h0 = __float2bfloat16(v.x);
    __nv_bfloat16 h1 = __float2bfloat16(v.y);
    __nv_bfloat16 h2 = __float2bfloat16(v.z);
    __nv_bfloat16 h3 = __float2bfloat16(v.w);
    hi[i + 0] = h0;
    hi[i + 1] = h1;
    hi[i + 2] = h2;
    hi[i + 3] = h3;
    lo[i + 0] = __float2bfloat16(v.x - __bfloat162float(h0));
    lo[i + 1] = __float2bfloat16(v.y - __bfloat162float(h1));
    lo[i + 2] = __float2bfloat16(v.z - __bfloat162float(h2));
    lo[i + 3] = __float2bfloat16(v.w - __bfloat162float(h3));
}

// ---------------- launch ----------------
extern "C" void kernel_launch(void* const* d_in, const int* in_sizes, int n_in,
                              void* d_out, int out_size) {
    const float* x  = (const float*)d_in[0];
    const float* wq = (const float*)d_in[1];
    const float* wk = (const float*)d_in[2];
    const float* wv = (const float*)d_in[3];
    const float* wo = (const float*)d_in[4];
    float* out = (float*)d_out;

    rope_table_kernel<<<256, 256>>>();
    const int cgrid = 1048576 / (256 * 4);
    conv_dev_kernel<<<cgrid, 256>>>(0, wq);
    conv_dev_kernel<<<cgrid, 256>>>(1, wk);
    conv_dev_kernel<<<cgrid, 256>>>(2, wv);
    conv_dev_kernel<<<cgrid, 256>>>(3, wo);
    conv_dev_kernel<<<cgrid * 4, 256>>>(4, x);
    mma_qkv_kernel<<<dim3(24, 32), 256>>>();
    attn_kernel<<<dim3(32, 32), 256>>>();
    conv_dev_kernel<<<cgrid * 4, 256>>>(5, (const float*)0);
    mma_out_kernel<<<dim3(8, 32), 256>>>(out);
}

// round 7
// speedup vs baseline: 2.6601x; 1.7270x over previous
#include <cuda_runtime.h>
#include <cuda_bf16.h>
#include <cstdint>
#include <math.h>

#define DIM   1024
#define NH    16
#define HD    64
#define HALF  32
#define BATCH 2
#define SEQ   2048
#define MTOT  (BATCH*SEQ)
#define NELEM (MTOT*DIM)
#define QKV_N (BATCH*NH*SEQ*HD)

// ---------------- scratch (device globals; no allocation allowed) ----------------
__device__ float g_cos[SEQ*HALF];
__device__ float g_sin[SEQ*HALF];
__device__ __nv_bfloat16 g_xh[NELEM];
__device__ __nv_bfloat16 g_xl[NELEM];
__device__ __nv_bfloat16 g_wh[NELEM];
__device__ __nv_bfloat16 g_wl[NELEM];
__device__ __nv_bfloat16 g_ah[NELEM];
__device__ __nv_bfloat16 g_al[NELEM];
__device__ __nv_bfloat16 q_hi[QKV_N];
__device__ __nv_bfloat16 q_lo[QKV_N];
__device__ __nv_bfloat16 k_hi[QKV_N];
__device__ __nv_bfloat16 k_lo[QKV_N];
__device__ __nv_bfloat16 v_hi[QKV_N];
__device__ __nv_bfloat16 v_lo[QKV_N];

// ---------------- RoPE tables ----------------
__global__ void rope_table_kernel() {
    int idx = blockIdx.x * blockDim.x + threadIdx.x;
    if (idx >= SEQ*HALF) return;
    int l = idx / HALF, i = idx % HALF;
    double invf = pow(10000.0, -(double)i / (double)HALF);
    double a = (double)l * invf;
    double s, c;
    sincos(a, &s, &c);
    g_cos[idx] = (float)c;
    g_sin[idx] = (float)s;
}

// ---------------- mma helpers ----------------
__device__ __forceinline__ void ldm4(uint32_t& r0, uint32_t& r1, uint32_t& r2, uint32_t& r3,
                                     uint32_t addr) {
    asm volatile("ldmatrix.sync.aligned.m8n8.x4.shared.b16 {%0,%1,%2,%3}, [%4];"
                 : "=r"(r0), "=r"(r1), "=r"(r2), "=r"(r3) : "r"(addr));
}

__device__ __forceinline__ void ldm4t(uint32_t& r0, uint32_t& r1, uint32_t& r2, uint32_t& r3,
                                      uint32_t addr) {
    asm volatile("ldmatrix.sync.aligned.m8n8.x4.trans.shared.b16 {%0,%1,%2,%3}, [%4];"
                 : "=r"(r0), "=r"(r1), "=r"(r2), "=r"(r3) : "r"(addr));
}

__device__ __forceinline__ void mma16816(float* c, const uint32_t* a, const uint32_t* b) {
    asm volatile("mma.sync.aligned.m16n8k16.row.col.f32.bf16.bf16.f32 "
                 "{%0,%1,%2,%3},{%4,%5,%6,%7},{%8,%9},{%0,%1,%2,%3};"
                 : "+f"(c[0]), "+f"(c[1]), "+f"(c[2]), "+f"(c[3])
                 : "r"(a[0]), "r"(a[1]), "r"(a[2]), "r"(a[3]), "r"(b[0]), "r"(b[1]));
}

__device__ __forceinline__ int sidx(int row, int c) {          // 32-col rows (GEMM tiles)
    return (row * 4 + (c ^ ((row >> 1) & 3))) * 8;
}

__device__ __forceinline__ int sidx64(int row, int c) {        // 64-col rows (attn tiles)
    return row * 64 + ((c ^ (row & 7)) << 3);
}

__device__ __forceinline__ void splitpack(float a, float b, uint32_t& hi, uint32_t& lo) {
    __nv_bfloat16 ha = __float2bfloat16(a);
    __nv_bfloat16 hb = __float2bfloat16(b);
    __nv_bfloat162 th;
    th.x = ha; th.y = hb;
    hi = *reinterpret_cast<uint32_t*>(&th);
    __nv_bfloat162 tl;
    tl.x = __float2bfloat16(a - __bfloat162float(ha));
    tl.y = __float2bfloat16(b - __bfloat162float(hb));
    lo = *reinterpret_cast<uint32_t*>(&tl);
}

// ---------------- core bf16x3 tile loop (GEMMs) -------------
__device__ __forceinline__ void mma_tile_loop(
    const __nv_bfloat16* __restrict__ Ah, const __nv_bfloat16* __restrict__ Al,
    const __nv_bfloat16* __restrict__ Bh, const __nv_bfloat16* __restrict__ Bl,
    int bm, int bnl, int lane, int wrp, int warpM, int warpN,
    __nv_bfloat16* sAh, __nv_bfloat16* sAl, __nv_bfloat16* sBh, __nv_bfloat16* sBl,
    float acc[4][4][4])
{
    const uint32_t bAh = (uint32_t)__cvta_generic_to_shared(sAh);
    const uint32_t bAl = (uint32_t)__cvta_generic_to_shared(sAl);
    const uint32_t bBh = (uint32_t)__cvta_generic_to_shared(sBh);
    const uint32_t bBl = (uint32_t)__cvta_generic_to_shared(sBl);

    for (int kt = 0; kt < 32; ++kt) {
        #pragma unroll
        for (int it = 0; it < 2; ++it) {
            int slot = lane + 32 * it;
            int row = 16 * wrp + (slot >> 2);
            int c = slot & 3;
            int so = sidx(row, c);
            size_t ga = (size_t)(bm * 128 + row) * 1024 + (size_t)(kt * 32 + c * 8);
            size_t gb = (size_t)(bnl * 128 + row) * 1024 + (size_t)(kt * 32 + c * 8);
            *(uint4*)(sAh + so) = *(const uint4*)(Ah + ga);
            *(uint4*)(sAl + so) = *(const uint4*)(Al + ga);
            *(uint4*)(sBh + so) = *(const uint4*)(Bh + gb);
            *(uint4*)(sBl + so) = *(const uint4*)(Bl + gb);
        }
        __syncthreads();

        #pragma unroll
        for (int kk = 0; kk < 2; ++kk) {
            uint32_t afh[4][4];
            uint32_t afl[4][4];
            #pragma unroll
            for (int mt = 0; mt < 4; ++mt) {
                int rA = 64 * warpM + 16 * mt + (lane & 7) + ((lane >> 3) & 1) * 8;
                int cA = 2 * kk + (lane >> 4);
                uint32_t off = (uint32_t)(sidx(rA, cA) * 2);
                ldm4(afh[mt][0], afh[mt][1], afh[mt][2], afh[mt][3], bAh + off);
                ldm4(afl[mt][0], afl[mt][1], afl[mt][2], afl[mt][3], bAl + off);
            }
            uint32_t bfh[4][2];
            uint32_t bfl[4][2];
            #pragma unroll
            for (int g2 = 0; g2 < 2; ++g2) {
                int rB = 8 * warpN + 64 * g2 + 32 * (lane >> 4) + (lane & 7);
                int cB = 2 * kk + ((lane >> 3) & 1);
                uint32_t off = (uint32_t)(sidx(rB, cB) * 2);
                uint32_t r0, r1, r2, r3;
                ldm4(r0, r1, r2, r3, bBh + off);
                bfh[2*g2][0] = r0;
                bfh[2*g2][1] = r1;
                bfh[2*g2+1][0] = r2;
                bfh[2*g2+1][1] = r3;
                ldm4(r0, r1, r2, r3, bBl + off);
                bfl[2*g2][0] = r0;
                bfl[2*g2][1] = r1;
                bfl[2*g2+1][0] = r2;
                bfl[2*g2+1][1] = r3;
            }
            #pragma unroll
            for (int mt = 0; mt < 4; ++mt) {
                #pragma unroll
                for (int tn = 0; tn < 4; ++tn) {
                    mma16816(acc[mt][tn], afh[mt], bfh[tn]);
                    mma16816(acc[mt][tn], afh[mt], bfl[tn]);
                    mma16816(acc[mt][tn], afl[mt], bfh[tn]);
                }
            }
        }
        __syncthreads();
    }
}

// ---------------- QKV GEMM + fused RoPE -> bf16 hi/lo outputs ----------------
// grid (24, 32): bn 0..7 -> Q, 8..15 -> K, 16..23 -> V.
__global__ void __launch_bounds__(256) mma_qkv_kernel() {
    __shared__ __align__(16) __nv_bfloat16 sAh[4096];
    __shared__ __align__(16) __nv_bfloat16 sAl[4096];
    __shared__ __align__(16) __nv_bfloat16 sBh[4096];
    __shared__ __align__(16) __nv_bfloat16 sBl[4096];

    const int tid = threadIdx.x;
    const int lane = tid & 31;
    const int wrp = tid >> 5;
    const int warpM = wrp >> 2;
    const int warpN = wrp & 3;
    const int bm = blockIdx.y;
    const int bn = blockIdx.x;
    const int wsel = bn >> 3;
    const int bnl = bn & 7;

    const __nv_bfloat16* Bh = g_wh + (size_t)wsel * 1048576u;
    const __nv_bfloat16* Bl = g_wl + (size_t)wsel * 1048576u;

    float acc[4][4][4];
    #pragma unroll
    for (int i = 0; i < 4; ++i) {
        #pragma unroll
        for (int j = 0; j < 4; ++j) {
            #pragma unroll
            for (int e = 0; e < 4; ++e) {
                acc[i][j][e] = 0.f;
            }
        }
    }

    mma_tile_loop(g_xh, g_xl, Bh, Bl, bm, bnl, lane, wrp, warpM, warpN,
                  sAh, sAl, sBh, sBl, acc);

    const int g = lane >> 2;
    const int tig = lane & 3;
    const bool is_v = (bn >= 16);
    __nv_bfloat16* dh = (bn < 8) ? q_hi : ((bn < 16) ? k_hi : v_hi);
    __nv_bfloat16* dl = (bn < 8) ? q_lo : ((bn < 16) ? k_lo : v_lo);

    #pragma unroll
    for (int mt = 0; mt < 4; ++mt) {
        #pragma unroll
        for (int eh = 0; eh < 2; ++eh) {
            int m = bm * 128 + 64 * warpM + 16 * mt + g + 8 * eh;
            int b_ = m >> 11;
            int l_ = m & 2047;
            if (!is_v) {
                #pragma unroll
                for (int el = 0; el < 2; ++el) {
                    int d2 = 8 * warpN + 2 * tig + el;
                    float cth = g_cos[l_ * HALF + d2];
                    float sth = g_sin[l_ * HALF + d2];
                    int e = 2 * eh + el;
                    float x1 = acc[mt][0][e];
                    float x2 = acc[mt][1][e];
                    acc[mt][0][e] = x1 * cth - x2 * sth;
                    acc[mt][1][e] = x2 * cth + x1 * sth;
                    x1 = acc[mt][2][e];
                    x2 = acc[mt][3][e];
                    acc[mt][2][e] = x1 * cth - x2 * sth;
                    acc[mt][3][e] = x2 * cth + x1 * sth;
                }
            }
            #pragma unroll
            for (int tn = 0; tn < 4; ++tn) {
                int n = bnl * 128 + 8 * warpN + 32 * tn + 2 * tig;
                int h = n >> 6;
                int d = n & 63;
                uint32_t hi, lo;
                splitpack(acc[mt][tn][2*eh], acc[mt][tn][2*eh+1], hi, lo);
                size_t idx = (((size_t)(b_ * NH + h)) * SEQ + l_) * HD + d;
                *(uint32_t*)&dh[idx] = hi;
                *(uint32_t*)&dl[idx] = lo;
            }
        }
    }
}

// ---------------- output projection GEMM ----------------
__global__ void __launch_bounds__(256) mma_out_kernel(float* __restrict__ out) {
    __shared__ __align__(16) __nv_bfloat16 sAh[4096];
    __shared__ __align__(16) __nv_bfloat16 sAl[4096];
    __shared__ __align__(16) __nv_bfloat16 sBh[4096];
    __shared__ __align__(16) __nv_bfloat16 sBl[4096];

    const int tid = threadIdx.x;
    const int lane = tid & 31;
    const int wrp = tid >> 5;
    const int warpM = wrp >> 2;
    const int warpN = wrp & 3;
    const int bm = blockIdx.y;
    const int bnl = blockIdx.x;

    const __nv_bfloat16* Bh = g_wh + (size_t)3 * 1048576u;
    const __nv_bfloat16* Bl = g_wl + (size_t)3 * 1048576u;

    float acc[4][4][4];
    #pragma unroll
    for (int i = 0; i < 4; ++i) {
        #pragma unroll
        for (int j = 0; j < 4; ++j) {
            #pragma unroll
            for (int e = 0; e < 4; ++e) {
                acc[i][j][e] = 0.f;
            }
        }
    }

    mma_tile_loop(g_ah, g_al, Bh, Bl, bm, bnl, lane, wrp, warpM, warpN,
                  sAh, sAl, sBh, sBl, acc);

    const int g = lane >> 2;
    const int tig = lane & 3;
    #pragma unroll
    for (int mt = 0; mt < 4; ++mt) {
        #pragma unroll
        for (int eh = 0; eh < 2; ++eh) {
            int m = bm * 128 + 64 * warpM + 16 * mt + g + 8 * eh;
            #pragma unroll
            for (int tn = 0; tn < 4; ++tn) {
                int n = bnl * 128 + 8 * warpN + 32 * tn + 2 * tig;
                float2 v2 = make_float2(acc[mt][tn][2*eh], acc[mt][tn][2*eh+1]);
                *(float2*)&out[(size_t)m * DIM + n] = v2;
            }
        }
    }
}

// ---------------- tensor-core flash attention (bf16x3) ----------------
// grid (16, 32): blockIdx.x = 128-row q tile, blockIdx.y = (b,h). 256 threads, 8 warps.
__global__ void __launch_bounds__(256) attn_mma_kernel() {
    __shared__ __align__(16) __nv_bfloat16 sm[16384];   // 32 KB
    __nv_bfloat16* sKh = sm;                 // 64x64
    __nv_bfloat16* sKl = sm + 4096;
    __nv_bfloat16* sVh = sm + 8192;
    __nv_bfloat16* sVl = sm + 12288;

    const int tid = threadIdx.x;
    const int lane = tid & 31;
    const int wrp = tid >> 5;
    const int qb = blockIdx.x;
    const int bh = blockIdx.y;

    const size_t base = (size_t)bh * SEQ * HD;
    const __nv_bfloat16* Qh = q_hi + base + (size_t)qb * 128 * HD;
    const __nv_bfloat16* Ql = q_lo + base + (size_t)qb * 128 * HD;
    const __nv_bfloat16* Kh = k_hi + base;
    const __nv_bfloat16* Kl = k_lo + base;
    const __nv_bfloat16* Vh = v_hi + base;
    const __nv_bfloat16* Vl = v_lo + base;

    const uint32_t smb = (uint32_t)__cvta_generic_to_shared(sm);
    const uint32_t bKh = smb;
    const uint32_t bKl = smb + 4096*2;
    const uint32_t bVh = smb + 8192*2;
    const uint32_t bVl = smb + 12288*2;

    // ---- stage Q (128x64 hi into sm[0..8191], lo into sm[8192..16383]) ----
    #pragma unroll
    for (int it = 0; it < 4; ++it) {
        int ci = tid + 256 * it;
        int row = ci >> 3;
        int c = ci & 7;
        int so = sidx64(row, c);
        *(uint4*)(sm + so) = *(const uint4*)(Qh + row * 64 + c * 8);
        *(uint4*)(sm + 8192 + so) = *(const uint4*)(Ql + row * 64 + c * 8);
    }
    __syncthreads();

    // ---- Q A-fragments, resident for whole kernel ----
    uint32_t aQh[4][4];
    uint32_t aQl[4][4];
    {
        int rA = 16 * wrp + (lane & 7) + ((lane >> 3) & 1) * 8;
        #pragma unroll
        for (int kc = 0; kc < 4; ++kc) {
            int cA = 2 * kc + (lane >> 4);
            uint32_t off = (uint32_t)(sidx64(rA, cA) * 2);
            ldm4(aQh[kc][0], aQh[kc][1], aQh[kc][2], aQh[kc][3], smb + off);
            ldm4(aQl[kc][0], aQl[kc][1], aQl[kc][2], aQl[kc][3], smb + 8192*2 + off);
        }
    }

    float Oacc[8][4];
    #pragma unroll
    for (int dt = 0; dt < 8; ++dt) {
        #pragma unroll
        for (int e = 0; e < 4; ++e) {
            Oacc[dt][e] = 0.f;
        }
    }
    float m0 = -INFINITY, m1 = -INFINITY, l0 = 0.f, l1 = 0.f;

    for (int kt = 0; kt < 32; ++kt) {
        __syncthreads();    // previous iteration done with K/V smem (and Q frags loaded)
        #pragma unroll
        for (int it = 0; it < 2; ++it) {
            int ci = tid + 256 * it;
            int row = ci >> 3;
            int c = ci & 7;
            int so = sidx64(row, c);
            size_t gl = (size_t)(kt * 64 + row) * 64 + c * 8;
            *(uint4*)(sKh + so) = *(const uint4*)(Kh + gl);
            *(uint4*)(sKl + so) = *(const uint4*)(Kl + gl);
            *(uint4*)(sVh + so) = *(const uint4*)(Vh + gl);
            *(uint4*)(sVl + so) = *(const uint4*)(Vl + gl);
        }
        __syncthreads();

        // ---- S = Q K^T (bf16x3) ----
        float S[8][4];
        #pragma unroll
        for (int st = 0; st < 8; ++st) {
            #pragma unroll
            for (int e = 0; e < 4; ++e) {
                S[st][e] = 0.f;
            }
        }

        #pragma unroll
        for (int kc = 0; kc < 4; ++kc) {
            uint32_t bkh[8][2];
            uint32_t bkl[8][2];
            int rB = (lane & 7) + 8 * (lane >> 4);
            int cB = 2 * kc + ((lane >> 3) & 1);
            #pragma unroll
            for (int nb = 0; nb < 4; ++nb) {
                int rr = 16 * nb + rB;
                uint32_t off = (uint32_t)(sidx64(rr, cB) * 2);
                uint32_t r0, r1, r2, r3;
                ldm4(r0, r1, r2, r3, bKh + off);
                bkh[2*nb][0] = r0;
                bkh[2*nb][1] = r1;
                bkh[2*nb+1][0] = r2;
                bkh[2*nb+1][1] = r3;
                ldm4(r0, r1, r2, r3, bKl + off);
                bkl[2*nb][0] = r0;
                bkl[2*nb][1] = r1;
                bkl[2*nb+1][0] = r2;
                bkl[2*nb+1][1] = r3;
            }
            #pragma unroll
            for (int st = 0; st < 8; ++st) {
                mma16816(S[st], aQh[kc], bkh[st]);
                mma16816(S[st], aQh[kc], bkl[st]);
                mma16816(S[st], aQl[kc], bkh[st]);
            }
        }

        // ---- online softmax (rows g and g+8 per thread) ----
        float mx0 = -INFINITY, mx1 = -INFINITY;
        #pragma unroll
        for (int st = 0; st < 8; ++st) {
            S[st][0] *= 0.125f;
            S[st][1] *= 0.125f;
            S[st][2] *= 0.125f;
            S[st][3] *= 0.125f;
            mx0 = fmaxf(mx0, fmaxf(S[st][0], S[st][1]));
            mx1 = fmaxf(mx1, fmaxf(S[st][2], S[st][3]));
        }
        #pragma unroll
        for (int msk = 1; msk < 4; msk <<= 1) {
            mx0 = fmaxf(mx0, __shfl_xor_sync(0xffffffffu, mx0, msk));
            mx1 = fmaxf(mx1, __shfl_xor_sync(0xffffffffu, mx1, msk));
        }
        float nm0 = fmaxf(m0, mx0);
        float nm1 = fmaxf(m1, mx1);
        float a0 = __expf(m0 - nm0);
        float a1 = __expf(m1 - nm1);
        m0 = nm0;
        m1 = nm1;
        float rs0 = 0.f, rs1 = 0.f;
        #pragma unroll
        for (int st = 0; st < 8; ++st) {
            S[st][0] = __expf(S[st][0] - nm0);
            S[st][1] = __expf(S[st][1] - nm0);
            S[st][2] = __expf(S[st][2] - nm1);
            S[st][3] = __expf(S[st][3] - nm1);
            rs0 += S[st][0] + S[st][1];
            rs1 += S[st][2] + S[st][3];
        }
        #pragma unroll
        for (int msk = 1; msk < 4; msk <<= 1) {
            rs0 += __shfl_xor_sync(0xffffffffu, rs0, msk);
            rs1 += __shfl_xor_sync(0xffffffffu, rs1, msk);
        }
        l0 = l0 * a0 + rs0;
        l1 = l1 * a1 + rs1;
        #pragma unroll
        for (int dt = 0; dt < 8; ++dt) {
            Oacc[dt][0] *= a0;
            Oacc[dt][1] *= a0;
            Oacc[dt][2] *= a1;
            Oacc[dt][3] *= a1;
        }

        // ---- pack P into A-fragments (hi/lo) ----
        uint32_t aPh[4][4];
        uint32_t aPl[4][4];
        #pragma unroll
        for (int kc = 0; kc < 4; ++kc) {
            splitpack(S[2*kc][0],   S[2*kc][1],   aPh[kc][0], aPl[kc][0]);
            splitpack(S[2*kc][2],   S[2*kc][3],   aPh[kc][1], aPl[kc][1]);
            splitpack(S[2*kc+1][0], S[2*kc+1][1], aPh[kc][2], aPl[kc][2]);
            splitpack(S[2*kc+1][2], S[2*kc+1][3], aPh[kc][3], aPl[kc][3]);
        }

        // ---- O += P V (bf16x3), V via ldmatrix.trans ----
        #pragma unroll
        for (int kc = 0; kc < 4; ++kc) {
            uint32_t bvh[8][2];
            uint32_t bvl[8][2];
            int tile = lane >> 3;
            int rowV = 16 * kc + (lane & 7) + 8 * (tile & 1);
            #pragma unroll
            for (int nb = 0; nb < 4; ++nb) {
                int cV = 2 * nb + (tile >> 1);
                uint32_t off = (uint32_t)(sidx64(rowV, cV) * 2);
                uint32_t r0, r1, r2, r3;
                ldm4t(r0, r1, r2, r3, bVh + off);
                bvh[2*nb][0] = r0;
                bvh[2*nb][1] = r1;
                bvh[2*nb+1][0] = r2;
                bvh[2*nb+1][1] = r3;
                ldm4t(r0, r1, r2, r3, bVl + off);
                bvl[2*nb][0] = r0;
                bvl[2*nb][1] = r1;
                bvl[2*nb+1][0] = r2;
                bvl[2*nb+1][1] = r3;
            }
            #pragma unroll
            for (int dt = 0; dt < 8; ++dt) {
                mma16816(Oacc[dt], aPh[kc], bvh[dt]);
                mma16816(Oacc[dt], aPh[kc], bvl[dt]);
                mma16816(Oacc[dt], aPl[kc], bvh[dt]);
            }
        }
    }

    // ---- epilogue: normalize, split hi/lo, write [B*L, D] ----
    const int g = lane >> 2;
    const int tig = lane & 3;
    const int b_ = bh >> 4;
    const int h = bh & 15;
    const int lr0 = qb * 128 + wrp * 16 + g;
    const int lr1 = lr0 + 8;
    float inv0 = 1.0f / l0;
    float inv1 = 1.0f / l1;
    #pragma unroll
    for (int dt = 0; dt < 8; ++dt) {
        int d = 8 * dt + 2 * tig;
        uint32_t hi, lo;
        splitpack(Oacc[dt][0] * inv0, Oacc[dt][1] * inv0, hi, lo);
        size_t i0 = ((size_t)(b_ * SEQ + lr0)) * DIM + h * 64 + d;
        *(uint32_t*)&g_ah[i0] = hi;
        *(uint32_t*)&g_al[i0] = lo;
        splitpack(Oacc[dt][2] * inv1, Oacc[dt][3] * inv1, hi, lo);
        size_t i1 = ((size_t)(b_ * SEQ + lr1)) * DIM + h * 64 + d;
        *(uint32_t*)&g_ah[i1] = hi;
        *(uint32_t*)&g_al[i1] = lo;
    }
}

// ---------------- fp32 -> bf16 hi/lo split ----------------
// which: 0..3 weight block -> g_wh/g_wl + which*1M; 4 -> x.
__global__ void conv_dev_kernel(int which, const float* __restrict__ src_param) {
    const float* src = src_param;
    __nv_bfloat16* hi;
    __nv_bfloat16* lo;
    if (which <= 3) {
        hi = g_wh + (size_t)which * 1048576u;
        lo = g_wl + (size_t)which * 1048576u;
    } else {
        hi = g_xh;
        lo = g_xl;
    }
    int i = (blockIdx.x * blockDim.x + threadIdx.x) * 4;
    float4 v = *(const float4*)(src + i);
    __nv_bfloat16 h0 = __float2bfloat16(v.x);
    __nv_bfloat16 h1 = __float2bfloat16(v.y);
    __nv_bfloat16 h2 = __float2bfloat16(v.z);
    __nv_bfloat16 h3 = __float2bfloat16(v.w);
    hi[i + 0] = h0;
    hi[i + 1] = h1;
    hi[i + 2] = h2;
    hi[i + 3] = h3;
    lo[i + 0] = __float2bfloat16(v.x - __bfloat162float(h0));
    lo[i + 1] = __float2bfloat16(v.y - __bfloat162float(h1));
    lo[i + 2] = __float2bfloat16(v.z - __bfloat162float(h2));
    lo[i + 3] = __float2bfloat16(v.w - __bfloat162float(h3));
}

// ---------------- launch ----------------
extern "C" void kernel_launch(void* const* d_in, const int* in_sizes, int n_in,
                              void* d_out, int out_size) {
    const float* x  = (const float*)d_in[0];
    const float* wq = (const float*)d_in[1];
    const float* wk = (const float*)d_in[2];
    const float* wv = (const float*)d_in[3];
    const float* wo = (const float*)d_in[4];
    float* out = (float*)d_out;

    rope_table_kernel<<<256, 256>>>();
    const int cgrid = 1048576 / (256 * 4);
    conv_dev_kernel<<<cgrid, 256>>>(0, wq);
    conv_dev_kernel<<<cgrid, 256>>>(1, wk);
    conv_dev_kernel<<<cgrid, 256>>>(2, wv);
    conv_dev_kernel<<<cgrid, 256>>>(3, wo);
    conv_dev_kernel<<<cgrid * 4, 256>>>(4, x);
    mma_qkv_kernel<<<dim3(24, 32), 256>>>();
    attn_mma_kernel<<<dim3(16, 32), 256>>>();
    mma_out_kernel<<<dim3(8, 32), 256>>>(out);
}